// round 3
// baseline (speedup 1.0000x reference)
#include <cuda_runtime.h>

// StateSpaceDiffusionModel: y[b,h,:] = causal_conv(u[b,h,:], f[h,:])
// reduced exactly to a scalar order-64 IIR+FIR (transposed direct form II):
//   y_t = c0*u_t + S[1]
//   S[i] <- S[i+1] + A'[i]*y_t + C'[i]*u_t   (merged delay line, i=1..64)
// A'[i] = a_{i-1}, C'[i] = c_i (i<=63).  a_j = w_j*P_j, c_i = k_i*P_i from
// the companion matrix M of the reference.

#define HH 512
#define NN 64
#define BB 16
#define LL 2048

__device__ float g_a[HH * NN];
__device__ float g_c[HH * NN];

// ---------------- Kernel 1: per-head coefficients (trivial) ----------------
__global__ void coef_kernel(const float* __restrict__ k) {
    __shared__ float sh[NN];
    __shared__ float shd[NN];
    __shared__ float shP[NN];
    __shared__ float shsum;
    int h = blockIdx.x;
    int j = threadIdx.x;
    float kv = k[h * NN + j];
    float kc = fminf(fmaxf(kv, 1.0f / 16.0f), 1.0f);
    sh[j] = kc;
    __syncthreads();
    if (j == 0) {
        float s = 0.f;
        for (int i = 0; i < NN; i++) s += sh[i];
        shsum = s;
    }
    __syncthreads();
    float kn = kc / shsum;                       // L1-normalized clamped k
    float s = (j < NN - 1) ? (1.0f + kn) : kn;   // column L1 norm of (A + b k^T)
    float w = kn / s;                            // M[0, j]
    shd[j] = 1.0f / s;                           // M[j+1, j] subdiagonal
    __syncthreads();
    if (j == 0) {
        float P = 1.f;
        for (int i = 0; i < NN; i++) { shP[i] = P; P *= shd[i]; }
    }
    __syncthreads();
    float Pj = shP[j];
    g_a[h * NN + j] = w * Pj;    // IIR taps
    g_c[h * NN + j] = kv * Pj;   // FIR taps (original k!)
}

// ---------------- packed f32x2 helpers ----------------
typedef unsigned long long ull;
__device__ __forceinline__ ull pack2(float lo, float hi) {
    ull r; asm("mov.b64 %0, {%1,%2};" : "=l"(r) : "f"(lo), "f"(hi)); return r;
}
__device__ __forceinline__ void unpack2(ull v, float& lo, float& hi) {
    asm("mov.b64 {%0,%1}, %2;" : "=f"(lo), "=f"(hi) : "l"(v));
}
__device__ __forceinline__ ull fma2(ull a, ull b, ull c) {
    ull d; asm("fma.rn.f32x2 %0, %1, %2, %3;" : "=l"(d) : "l"(a), "l"(b), "l"(c)); return d;
}

// ---------------- Kernel 2: fused scan, 8 lanes per sequence ----------------
// Two timesteps per iteration. pair p = slots (2p+1, 2p+2), p = 0..31.
//   S''_p = S_{p+1} + Ae_p*y0 + Ao_p*y1 + Ce_p*u0 + Co_p*u1
// Warp = 4 sequences x 8 lanes; lane r owns pairs 4r..4r+3 (slots 8r+1..8r+8).
// 2048 warps total (~3.5 per SMSP) so shfl/chain latency is hidden.
// u read as float4 (2 iterations per load) through a 4-slot register FIFO
// (prefetch distance 8 iterations); y written as float4 every 2 iterations.
#define PD2 4   // float4 FIFO slots; each slot feeds 2 iterations (4 timesteps)

__global__ void __launch_bounds__(128, 4)
scan_kernel(const float* __restrict__ u, float* __restrict__ y) {
    int warp = blockIdx.x * (blockDim.x >> 5) + (threadIdx.x >> 5);
    int lane = threadIdx.x & 31;
    int g = lane >> 3;   // sequence within warp (0..3)
    int r = lane & 7;    // lane within group (0..7)
    int leader = lane & ~7;
    int seq = warp * 4 + g;           // 0..8191
    int h = seq & (HH - 1);
    const float4* ubase4 = (const float4*)(u + (size_t)seq * LL);
    float4* ybase4 = (float4*)(y + (size_t)seq * LL);

    const float* ah = g_a + h * NN;
    const float* ch = g_c + h * NN;

    ull Ae[4], Ao[4], Ce[4], Co[4], S[4];
#pragma unroll
    for (int i = 0; i < 4; i++) {
        int p = r * 4 + i;
        int i1 = 2 * p + 1, i2 = 2 * p + 2, i3 = 2 * p + 3;
        // A'[idx] = a[idx-1] for 1<=idx<=64 ; C'[idx] = c[idx] for 1<=idx<=63
        float A1 = (i1 <= 64) ? ah[i1 - 1] : 0.f;
        float A2 = (i2 <= 64) ? ah[i2 - 1] : 0.f;
        float A3 = (i3 <= 64) ? ah[i3 - 1] : 0.f;
        float C1 = (i1 <= 63) ? ch[i1] : 0.f;
        float C2 = (i2 <= 63) ? ch[i2] : 0.f;
        float C3 = (i3 <= 63) ? ch[i3] : 0.f;
        Ae[i] = pack2(A2, A3);
        Ao[i] = pack2(A1, A2);
        Ce[i] = pack2(C2, C3);
        Co[i] = pack2(C1, C2);
        S[i] = 0ull;
    }
    float c0h = ch[0], c1h = ch[1], a0h = ah[0];
    float SS1 = 0.f, SS2 = 0.f;   // unpacked old S[0] (valid on r==0)

    // prologue: fill FIFO (each slot covers 4 timesteps)
    float4 buf[PD2];
#pragma unroll
    for (int j = 0; j < PD2; j++)
        buf[j] = ubase4[j];

    const int NQ = LL / 4;  // 512 four-step chunks
    for (int q0 = 0; q0 < NQ; q0 += PD2) {
#pragma unroll
        for (int j = 0; j < PD2; j++) {
            int q = q0 + j;             // chunk index: timesteps 4q..4q+3
            float4 cur = buf[j];
            int qp = q + PD2;
            if (qp > NQ - 1) qp = NQ - 1;   // clamped refill (unused if OOB)
            buf[j] = ubase4[qp];

            float2 yout01, yout23;
            // ---- iteration A: timesteps 4q, 4q+1 (u = cur.x, cur.y) ----
            {
                ull sn = __shfl_down_sync(0xffffffffu, S[0], 1);
                if (r == 7) sn = 0ull;
                float u0 = cur.x, u1 = cur.y;
                float y0 = fmaf(c0h, u0, SS1);
                float y1 = fmaf(a0h, y0, fmaf(c1h, u0, fmaf(c0h, u1, SS2)));
                ull ypk = __shfl_sync(0xffffffffu, pack2(y0, y1), leader);
                float y0b, y1b; unpack2(ypk, y0b, y1b);
                ull y0pk = pack2(y0b, y0b), y1pk = pack2(y1b, y1b);
                ull u0pk = pack2(u0, u0), u1pk = pack2(u1, u1);
#pragma unroll
                for (int i = 0; i < 3; i++)
                    S[i] = fma2(Ae[i], y0pk, fma2(Ao[i], y1pk,
                            fma2(Ce[i], u0pk, fma2(Co[i], u1pk, S[i + 1]))));
                S[3] = fma2(Ae[3], y0pk, fma2(Ao[3], y1pk,
                         fma2(Ce[3], u0pk, fma2(Co[3], u1pk, sn))));
                unpack2(S[0], SS1, SS2);
                yout01 = make_float2(y0, y1);
            }
            // ---- iteration B: timesteps 4q+2, 4q+3 (u = cur.z, cur.w) ----
            {
                ull sn = __shfl_down_sync(0xffffffffu, S[0], 1);
                if (r == 7) sn = 0ull;
                float u0 = cur.z, u1 = cur.w;
                float y0 = fmaf(c0h, u0, SS1);
                float y1 = fmaf(a0h, y0, fmaf(c1h, u0, fmaf(c0h, u1, SS2)));
                ull ypk = __shfl_sync(0xffffffffu, pack2(y0, y1), leader);
                float y0b, y1b; unpack2(ypk, y0b, y1b);
                ull y0pk = pack2(y0b, y0b), y1pk = pack2(y1b, y1b);
                ull u0pk = pack2(u0, u0), u1pk = pack2(u1, u1);
#pragma unroll
                for (int i = 0; i < 3; i++)
                    S[i] = fma2(Ae[i], y0pk, fma2(Ao[i], y1pk,
                            fma2(Ce[i], u0pk, fma2(Co[i], u1pk, S[i + 1]))));
                S[3] = fma2(Ae[3], y0pk, fma2(Ao[3], y1pk,
                         fma2(Ce[3], u0pk, fma2(Co[3], u1pk, sn))));
                unpack2(S[0], SS1, SS2);
                yout23 = make_float2(y0, y1);
            }

            if (r == 0)
                ybase4[q] = make_float4(yout01.x, yout01.y, yout23.x, yout23.y);
        }
    }
}

extern "C" void kernel_launch(void* const* d_in, const int* in_sizes, int n_in,
                              void* d_out, int out_size) {
    const float* u = (const float*)d_in[0];
    const float* k = (const float*)d_in[1];
    if (n_in >= 2 && in_sizes[0] == HH * NN) {  // defensive: swap if order differs
        u = (const float*)d_in[1];
        k = (const float*)d_in[0];
    }
    float* y = (float*)d_out;

    coef_kernel<<<HH, NN>>>(k);
    // 8192 sequences, 4 per warp, 4 warps per 128-thread CTA -> 512 CTAs
    scan_kernel<<<(BB * HH) / 16, 128>>>(u, y);
}